// round 6
// baseline (speedup 1.0000x reference)
#include <cuda_runtime.h>
#include <cuda_bf16.h>
#include <math.h>

#define NB_   128
#define TT_   128
#define NN_   8
#define NTOT  (NB_*TT_*NN_)        // 131072 rows
#define CCH   64
#define F1    32
#define EDG   1048576

// ---------------- device scratch (static allocation only) ----------------
__device__ float g_hW  [NTOT*CCH];   // 32MB : GEMM out / conv out (ping, row-matrix layout)
__device__ float g_bufA[NTOT*CCH];   // 32MB : GCN aggregate (row-matrix layout)
__device__ float g_bufB[NTOT*CCH];   // 32MB : layer output in FLAT [B,C,NN,T] view order
__device__ float g_dinv[NTOT];
__device__ int   g_deg  [NTOT];
__device__ int   g_rowptr[NTOT+1];
__device__ int   g_cursor[NTOT];
__device__ int   g_csr [EDG];
__device__ float g_coef[EDG];        // 4MB : dinv[src]*dinv[dst] per CSR slot
__device__ int   g_bsum[512];
__device__ float g_stats[256];       // [0:64] sum  [64:128] sumsq  [128:192] a  [192:256] b'
__device__ float g_wbar[65];

// ---------------- degree / CSR build ----------------
__global__ void k_zero_deg() {
    int i = blockIdx.x*blockDim.x + threadIdx.x;
    if (i < NTOT) g_deg[i] = 0;
}
__global__ void k_count(const int* __restrict__ dst) {
    int e = blockIdx.x*blockDim.x + threadIdx.x;
    if (e < EDG) atomicAdd(&g_deg[dst[e]], 1);
}
__global__ void k_dinv() {
    int i = blockIdx.x*blockDim.x + threadIdx.x;
    if (i < NTOT) g_dinv[i] = rsqrtf((float)(g_deg[i] + 1));
}
__global__ void k_scan1() {   // 512 blocks x 256
    __shared__ int s[256];
    int tid = threadIdx.x, i = blockIdx.x*256 + tid;
    int v = g_deg[i];
    s[tid] = v; __syncthreads();
    #pragma unroll
    for (int off = 1; off < 256; off <<= 1) {
        int t = (tid >= off) ? s[tid-off] : 0;
        __syncthreads();
        s[tid] += t;
        __syncthreads();
    }
    g_rowptr[i] = s[tid] - v;            // exclusive within block
    if (tid == 255) g_bsum[blockIdx.x] = s[255];
}
__global__ void k_scan2() {   // 1 block x 512
    __shared__ int s[512];
    int tid = threadIdx.x;
    int v = g_bsum[tid];
    s[tid] = v; __syncthreads();
    #pragma unroll
    for (int off = 1; off < 512; off <<= 1) {
        int t = (tid >= off) ? s[tid-off] : 0;
        __syncthreads();
        s[tid] += t;
        __syncthreads();
    }
    g_bsum[tid] = s[tid] - v;            // exclusive block offsets
}
__global__ void k_scan3() {
    int i = blockIdx.x*blockDim.x + threadIdx.x;
    if (i < NTOT) {
        int r = g_rowptr[i] + g_bsum[i >> 8];
        g_rowptr[i] = r;
        g_cursor[i] = r;
    }
    if (i == 0) g_rowptr[NTOT] = EDG;
}
// fill CSR slots AND precompute per-edge coefficient dinv[s]*dinv[d]
// (g_dinv is finalized before this kernel launches)
__global__ void k_fill(const int* __restrict__ src, const int* __restrict__ dst) {
    int e = blockIdx.x*blockDim.x + threadIdx.x;
    if (e < EDG) {
        int d = dst[e];
        int s = src[e];
        int slot = atomicAdd(&g_cursor[d], 1);
        g_csr [slot] = s;
        g_coef[slot] = g_dinv[s]*g_dinv[d];
    }
}

// ---------------- GEMM: hW = X @ W ; bufA = bias + hW*dinv^2 (self-loop) ----------------
template<int F>
__device__ __forceinline__
void gemm_body(const float* __restrict__ X, const float* __restrict__ W,
               const float* __restrict__ bias) {
    __shared__ float4 ws[F*16];
    __shared__ float  bs[64];
    int tid = threadIdx.x;
    for (int i = tid; i < F*16; i += 256) ws[i] = ((const float4*)W)[i];
    if (tid < 64) bs[tid] = bias[tid];
    __syncthreads();

    int row = blockIdx.x*256 + tid;
    if (row >= NTOT) return;

    float4 acc[16];
    #pragma unroll
    for (int j = 0; j < 16; j++) acc[j] = make_float4(0.f,0.f,0.f,0.f);

    const float4* xp = (const float4*)(X + (size_t)row*F);
    #pragma unroll
    for (int c4 = 0; c4 < F/4; c4++) {
        float4 xv = xp[c4];
        int ci0 = c4*4;
        #pragma unroll
        for (int l = 0; l < 4; l++) {
            float xs = (l==0)?xv.x:(l==1)?xv.y:(l==2)?xv.z:xv.w;
            #pragma unroll
            for (int j = 0; j < 16; j++) {
                float4 w = ws[(ci0+l)*16 + j];
                acc[j].x += xs*w.x; acc[j].y += xs*w.y;
                acc[j].z += xs*w.z; acc[j].w += xs*w.w;
            }
        }
    }
    float dv = g_dinv[row], d2 = dv*dv;
    float4* hp = (float4*)(g_hW   + (size_t)row*64);
    float4* ap = (float4*)(g_bufA + (size_t)row*64);
    #pragma unroll
    for (int j = 0; j < 16; j++) {
        hp[j] = acc[j];
        float4 b4 = ((const float4*)bs)[j];
        ap[j] = make_float4(b4.x + acc[j].x*d2, b4.y + acc[j].y*d2,
                            b4.z + acc[j].z*d2, b4.w + acc[j].w*d2);
    }
}

__global__ __launch_bounds__(256)
void k_gemm1(const float* __restrict__ X, const float* __restrict__ W,
             const float* __restrict__ bias) {
    gemm_body<F1>(X, W, bias);
}
// layer-2 GEMM: view rows of the flat [B,C,NN,T] tensor ARE contiguous 64-float
// chunks, so reading g_bufB at row*64 reproduces x.view(-1, 64) exactly.
__global__ __launch_bounds__(256)
void k_gemm2(const float* __restrict__ W, const float* __restrict__ bias) {
    gemm_body<CCH>(g_bufB, W, bias);
}

// ---------------- edge aggregation: warp per dst node, atomic-free --------------
// Precomputed g_coef removes the dependent dinv[s] load: per step only the row
// load depends on the (warp-uniform) index load; csr/coef loads are independent.
__global__ __launch_bounds__(256)
void k_gather() {
    int g = blockIdx.x*blockDim.x + threadIdx.x;
    int node = g >> 5, lane = g & 31;
    if (node >= NTOT) return;
    int beg = g_rowptr[node], end = g_rowptr[node+1];
    float2* arow = (float2*)(g_bufA + (size_t)node*64);
    float2 acc = arow[lane];
    int j = beg;
    for (; j + 1 < end; j += 2) {
        int   s0 = g_csr [j],   s1 = g_csr [j+1];
        float c0 = g_coef[j],   c1 = g_coef[j+1];
        float2 v0 = ((const float2*)(g_hW + (size_t)s0*64))[lane];
        float2 v1 = ((const float2*)(g_hW + (size_t)s1*64))[lane];
        acc.x += c0*v0.x + c1*v1.x;
        acc.y += c0*v0.y + c1*v1.y;
    }
    if (j < end) {
        int   s0 = g_csr [j];
        float c0 = g_coef[j];
        float2 v0 = ((const float2*)(g_hW + (size_t)s0*64))[lane];
        acc.x += c0*v0.x; acc.y += c0*v0.y;
    }
    arow[lane] = acc;
}

// ---------------- temporal conv (1x3 along T), bufA -> hW (row-matrix) ----------------
#define IN_STRIDE 68
#define SMEM_CONV ((130*IN_STRIDE + 3*64*64 + 64) * 4)
__global__ __launch_bounds__(128)
void k_conv(const float* __restrict__ tw, const float* __restrict__ tb) {
    extern __shared__ float sm[];
    float* in_s = sm;                       // [130][68], row r = t+1
    float* w_s  = sm + 130*IN_STRIDE;       // [k][ci][co]
    float* tb_s = w_s + 3*64*64;

    int bn = blockIdx.x;                    // 0..1023 = b*8+n
    int b = bn >> 3, n = bn & 7;
    int tid = threadIdx.x;

    for (int i = tid; i < 64*64*3; i += 128) {
        int co = i / 192, rem = i % 192, ci = rem / 3, k = rem % 3;
        w_s[(k*64 + ci)*64 + co] = tw[i];
    }
    if (tid < 64) tb_s[tid] = tb[tid];
    for (int i = tid; i < IN_STRIDE; i += 128) {
        in_s[i] = 0.f;
        in_s[129*IN_STRIDE + i] = 0.f;
    }
    const float* base = g_bufA + ((size_t)(b*TT_)*NN_ + n)*64;
    for (int i = tid; i < 128*16; i += 128) {
        int t = i >> 4, j = i & 15;
        float4 v = ((const float4*)(base + (size_t)t*NN_*64))[j];
        float* p = in_s + (t+1)*IN_STRIDE + j*4;
        p[0]=v.x; p[1]=v.y; p[2]=v.z; p[3]=v.w;
    }
    __syncthreads();

    int tg = tid >> 3, cg = tid & 7;
    int t0 = tg*8, co0 = cg*8;
    float acc[8][8];
    #pragma unroll
    for (int tt = 0; tt < 8; tt++)
        #pragma unroll
        for (int cc = 0; cc < 8; cc++) acc[tt][cc] = tb_s[co0+cc];

    for (int ci = 0; ci < 64; ci++) {
        float xv[10];
        #pragma unroll
        for (int i = 0; i < 10; i++) xv[i] = in_s[(t0+i)*IN_STRIDE + ci];
        float wv[24];
        #pragma unroll
        for (int k = 0; k < 3; k++) {
            const float4* wp = (const float4*)(w_s + ((k*64 + ci) << 6) + co0);
            float4 a = wp[0], c = wp[1];
            wv[k*8+0]=a.x; wv[k*8+1]=a.y; wv[k*8+2]=a.z; wv[k*8+3]=a.w;
            wv[k*8+4]=c.x; wv[k*8+5]=c.y; wv[k*8+6]=c.z; wv[k*8+7]=c.w;
        }
        #pragma unroll
        for (int tt = 0; tt < 8; tt++)
            #pragma unroll
            for (int k = 0; k < 3; k++) {
                float xs = xv[tt+k];
                #pragma unroll
                for (int cc = 0; cc < 8; cc++)
                    acc[tt][cc] += xs*wv[k*8+cc];
            }
    }
    #pragma unroll
    for (int tt = 0; tt < 8; tt++) {
        float* op = g_hW + (((size_t)((b*TT_ + t0+tt)*NN_ + n)) << 6) + co0;
        ((float4*)op)[0] = make_float4(acc[tt][0],acc[tt][1],acc[tt][2],acc[tt][3]);
        ((float4*)op)[1] = make_float4(acc[tt][4],acc[tt][5],acc[tt][6],acc[tt][7]);
    }
}

// ---------------- BN batch stats over hW (row-matrix: channel = column) ----------------
__global__ void k_zero_stats() {
    int t = threadIdx.x;
    if (t < 128) g_stats[t] = 0.f;
}
__global__ __launch_bounds__(256)
void k_stats() {   // grid 512
    __shared__ float ssum[256], ssq[256];
    int tid = threadIdx.x, c = tid & 63, rep = tid >> 6;
    float s = 0.f, q = 0.f;
    for (int r = blockIdx.x*4 + rep; r < NTOT; r += 512*4) {
        float v = g_hW[(size_t)r*64 + c];
        s += v; q += v*v;
    }
    ssum[tid] = s; ssq[tid] = q; __syncthreads();
    if (tid < 64) {
        s = ssum[tid] + ssum[tid+64] + ssum[tid+128] + ssum[tid+192];
        q = ssq [tid] + ssq [tid+64] + ssq [tid+128] + ssq [tid+192];
        atomicAdd(&g_stats[tid], s);
        atomicAdd(&g_stats[64+tid], q);
    }
}
__global__ void k_stats_fin(const float* __restrict__ gam, const float* __restrict__ bet) {
    int c = threadIdx.x;
    if (c < 64) {
        float inv = 1.f/(float)NTOT;
        float mean = g_stats[c]*inv;
        float var  = g_stats[64+c]*inv - mean*mean;
        float a = gam[c]*rsqrtf(var + 1e-5f);
        g_stats[128+c] = a;
        g_stats[192+c] = bet[c] - mean*a;
    }
}

// ---------------- fused BN+ReLU+1x1conv+tanh : hW(rowmat) -> bufB(FLAT [B,C,NN,T]) ----
// Faithful to the reference's x.view(-1, C) quirk: the layer output row-matrix is the
// raw row-major flatten of [B, C, NN, T]. We materialize that flat order here via an
// smem transpose tile so stores stay 128B-contiguous.
// Block = 256 consecutive rows r = (b, t in [t0,t0+32), n in [0,8)).
// Element (row=(b,t,n), co) -> flat offset ((b*64+co)*8+n)*128 + t.
#define RS 257
#define SMEM_FUSED (64*RS*4)
__global__ __launch_bounds__(256)
void k_fused(const float* __restrict__ ow, const float* __restrict__ ob) {
    __shared__ float wt[64*64];   // transposed [ci][co]
    __shared__ float sa[64], sb[64], sob[64];
    extern __shared__ float sm_t[];   // [64 co][RS rows]
    int tid = threadIdx.x;
    for (int i = tid; i < 4096; i += 256) {
        int co = i >> 6, ci = i & 63;
        wt[ci*64 + co] = ow[i];
    }
    if (tid < 64) {
        sa[tid] = g_stats[128+tid];
        sb[tid] = g_stats[192+tid];
        sob[tid] = ob[tid];
    }
    __syncthreads();

    int row = blockIdx.x*256 + tid;   // grid covers NTOT exactly
    const float4* yp = (const float4*)(g_hW + (size_t)row*64);
    float4 acc[16];
    #pragma unroll
    for (int j = 0; j < 16; j++) acc[j] = ((const float4*)sob)[j];

    #pragma unroll
    for (int c4 = 0; c4 < 16; c4++) {
        float4 yv = yp[c4];
        int ci0 = c4*4;
        #pragma unroll
        for (int l = 0; l < 4; l++) {
            float y = (l==0)?yv.x:(l==1)?yv.y:(l==2)?yv.z:yv.w;
            int ci = ci0 + l;
            float u = fmaxf(sa[ci]*y + sb[ci], 0.f);
            const float4* wp = (const float4*)(wt + ci*64);
            #pragma unroll
            for (int j = 0; j < 16; j++) {
                float4 w = wp[j];
                acc[j].x += u*w.x; acc[j].y += u*w.y;
                acc[j].z += u*w.z; acc[j].w += u*w.w;
            }
        }
    }
    // stage tanh output into smem tile: sm_t[co][tid], tid = tloc*8 + n
    #pragma unroll
    for (int j = 0; j < 16; j++) {
        sm_t[(j*4+0)*RS + tid] = tanhf(acc[j].x);
        sm_t[(j*4+1)*RS + tid] = tanhf(acc[j].y);
        sm_t[(j*4+2)*RS + tid] = tanhf(acc[j].z);
        sm_t[(j*4+3)*RS + tid] = tanhf(acc[j].w);
    }
    __syncthreads();

    // scatter to flat [B,C,NN,T]: each thread writes 2 runs of 32 contiguous t
    int b  = blockIdx.x >> 2;
    int t0 = (blockIdx.x & 3) * 32;
    #pragma unroll
    for (int k = 0; k < 2; k++) {
        int q  = k*256 + tid;           // run id: q = n*64 + co
        int n  = q >> 6, co = q & 63;
        float4* dp = (float4*)(g_bufB + (((size_t)(b*64 + co)*8 + n)*128 + t0));
        const float* sp = sm_t + co*RS + n;
        #pragma unroll
        for (int i = 0; i < 8; i++) {
            int tl = i*4;
            dp[i] = make_float4(sp[(tl+0)*8], sp[(tl+1)*8],
                                sp[(tl+2)*8], sp[(tl+3)*8]);
        }
    }
}

// ---------------- head: out[b,n] = (1/T) sum_t viewrow . wbar + bbar ----------------
// Final view rows r=(b*128+t)*8+n live at flat offset r*64 in bufB — exactly the
// addressing below.
__global__ void k_wbar(const float* __restrict__ rw, const float* __restrict__ rb) {
    int c = threadIdx.x;
    if (c < 64) {
        float s = 0.f;
        #pragma unroll
        for (int j = 0; j < 8; j++) s += rw[c*8 + j];
        g_wbar[c] = s*0.125f;
    }
    if (c == 64) {
        float s = 0.f;
        #pragma unroll
        for (int j = 0; j < 8; j++) s += rb[j];
        g_wbar[64] = s*0.125f;
    }
}
__global__ __launch_bounds__(128)
void k_head(float* __restrict__ out) {
    __shared__ float sw[64];
    __shared__ float red[128];
    int bn = blockIdx.x;                 // b*8+n
    int b = bn >> 3, n = bn & 7;
    int tid = threadIdx.x;               // = t
    if (tid < 64) sw[tid] = g_wbar[tid];
    __syncthreads();
    const float4* rp = (const float4*)(g_bufB + (((size_t)((b*TT_ + tid)*NN_ + n)) << 6));
    float s = 0.f;
    #pragma unroll
    for (int j = 0; j < 16; j++) {
        float4 v = rp[j];
        float4 w = ((const float4*)sw)[j];
        s += v.x*w.x + v.y*w.y + v.z*w.z + v.w*w.w;
    }
    red[tid] = s; __syncthreads();
    #pragma unroll
    for (int off = 64; off > 0; off >>= 1) {
        if (tid < off) red[tid] += red[tid+off];
        __syncthreads();
    }
    if (tid == 0) out[bn] = red[0]*(1.f/128.f) + g_wbar[64];
}

// ---------------- launch ----------------
extern "C" void kernel_launch(void* const* d_in, const int* in_sizes, int n_in,
                              void* d_out, int out_size) {
    const float* x      = (const float*)d_in[0];
    const int*   ei     = (const int*)d_in[1];
    const float* gcn1_w = (const float*)d_in[2];
    const float* gcn1_b = (const float*)d_in[3];
    const float* t1_w   = (const float*)d_in[4];
    const float* t1_b   = (const float*)d_in[5];
    const float* bn1_g  = (const float*)d_in[6];
    const float* bn1_b  = (const float*)d_in[7];
    const float* o1_w   = (const float*)d_in[8];
    const float* o1_b   = (const float*)d_in[9];
    const float* gcn2_w = (const float*)d_in[10];
    const float* gcn2_b = (const float*)d_in[11];
    const float* t2_w   = (const float*)d_in[12];
    const float* t2_b   = (const float*)d_in[13];
    const float* bn2_g  = (const float*)d_in[14];
    const float* bn2_b  = (const float*)d_in[15];
    const float* o2_w   = (const float*)d_in[16];
    const float* o2_b   = (const float*)d_in[17];
    const float* reg_w  = (const float*)d_in[18];
    const float* reg_b  = (const float*)d_in[19];
    const int* src = ei;
    const int* dst = ei + EDG;

    cudaFuncSetAttribute(k_conv,  cudaFuncAttributeMaxDynamicSharedMemorySize, SMEM_CONV);
    cudaFuncSetAttribute(k_fused, cudaFuncAttributeMaxDynamicSharedMemorySize, SMEM_FUSED);

    const int NBLK = NTOT/256;       // 512

    // graph normalization + CSR (shared by both layers)
    k_zero_deg<<<NBLK,256>>>();
    k_count<<<EDG/256,256>>>(dst);
    k_dinv<<<NBLK,256>>>();
    k_scan1<<<512,256>>>();
    k_scan2<<<1,512>>>();
    k_scan3<<<NBLK,256>>>();
    k_fill<<<EDG/256,256>>>(src, dst);

    // ---- layer 1 ----
    k_gemm1<<<NBLK,256>>>(x, gcn1_w, gcn1_b);
    k_gather<<<NTOT*32/256,256>>>();
    k_conv<<<NB_*NN_,128,SMEM_CONV>>>(t1_w, t1_b);
    k_zero_stats<<<1,128>>>();
    k_stats<<<512,256>>>();
    k_stats_fin<<<1,64>>>(bn1_g, bn1_b);
    k_fused<<<NBLK,256,SMEM_FUSED>>>(o1_w, o1_b);

    // ---- layer 2 ----
    k_gemm2<<<NBLK,256>>>(gcn2_w, gcn2_b);
    k_gather<<<NTOT*32/256,256>>>();
    k_conv<<<NB_*NN_,128,SMEM_CONV>>>(t2_w, t2_b);
    k_zero_stats<<<1,128>>>();
    k_stats<<<512,256>>>();
    k_stats_fin<<<1,64>>>(bn2_g, bn2_b);
    k_fused<<<NBLK,256,SMEM_FUSED>>>(o2_w, o2_b);

    // ---- head ----
    k_wbar<<<1,128>>>(reg_w, reg_b);
    k_head<<<NB_*NN_,128>>>((float*)d_out);
}

// round 13
// speedup vs baseline: 1.0109x; 1.0109x over previous
#include <cuda_runtime.h>
#include <cuda_bf16.h>
#include <math.h>

#define NB_   128
#define TT_   128
#define NN_   8
#define NTOT  (NB_*TT_*NN_)        // 131072 rows
#define CCH   64
#define F1    32
#define EDG   1048576

typedef unsigned long long u64;

// packed f32x2 helpers (sm_103a): lane-wise fma on two fp32 packed in 64 bits
__device__ __forceinline__ u64 ffma2(u64 a, u64 b, u64 c) {
    u64 d; asm("fma.rn.f32x2 %0, %1, %2, %3;" : "=l"(d) : "l"(a), "l"(b), "l"(c));
    return d;
}
__device__ __forceinline__ u64 bcast2(float x) {
    u64 d; asm("mov.b64 %0, {%1, %1};" : "=l"(d) : "r"(__float_as_uint(x)));
    return d;
}

// ---------------- device scratch (static allocation only) ----------------
__device__ float g_hW  [NTOT*CCH];   // 32MB : GEMM out / conv out (ping, row-matrix layout)
__device__ float g_bufA[NTOT*CCH];   // 32MB : GCN aggregate (row-matrix layout)
__device__ float g_bufB[NTOT*CCH];   // 32MB : layer output in FLAT [B,C,NN,T] view order
__device__ float g_dinv[NTOT];
__device__ int   g_deg  [NTOT];
__device__ int   g_rowptr[NTOT+1];
__device__ int   g_cursor[NTOT];
__device__ int   g_csr [EDG];
__device__ float g_coef[EDG];        // 4MB : dinv[src]*dinv[dst] per CSR slot
__device__ int   g_bsum[512];
__device__ float g_stats[256];       // [0:64] sum  [64:128] sumsq  [128:192] a  [192:256] b'
__device__ float g_wbar[65];

// ---------------- degree / CSR build ----------------
__global__ void k_zero_deg() {
    int i = blockIdx.x*blockDim.x + threadIdx.x;
    if (i < NTOT) g_deg[i] = 0;
}
__global__ void k_count(const int* __restrict__ dst) {
    int e = blockIdx.x*blockDim.x + threadIdx.x;
    if (e < EDG) atomicAdd(&g_deg[dst[e]], 1);
}
__global__ void k_dinv() {
    int i = blockIdx.x*blockDim.x + threadIdx.x;
    if (i < NTOT) g_dinv[i] = rsqrtf((float)(g_deg[i] + 1));
}
__global__ void k_scan1() {   // 512 blocks x 256
    __shared__ int s[256];
    int tid = threadIdx.x, i = blockIdx.x*256 + tid;
    int v = g_deg[i];
    s[tid] = v; __syncthreads();
    #pragma unroll
    for (int off = 1; off < 256; off <<= 1) {
        int t = (tid >= off) ? s[tid-off] : 0;
        __syncthreads();
        s[tid] += t;
        __syncthreads();
    }
    g_rowptr[i] = s[tid] - v;            // exclusive within block
    if (tid == 255) g_bsum[blockIdx.x] = s[255];
}
__global__ void k_scan2() {   // 1 block x 512
    __shared__ int s[512];
    int tid = threadIdx.x;
    int v = g_bsum[tid];
    s[tid] = v; __syncthreads();
    #pragma unroll
    for (int off = 1; off < 512; off <<= 1) {
        int t = (tid >= off) ? s[tid-off] : 0;
        __syncthreads();
        s[tid] += t;
        __syncthreads();
    }
    g_bsum[tid] = s[tid] - v;            // exclusive block offsets
}
__global__ void k_scan3() {
    int i = blockIdx.x*blockDim.x + threadIdx.x;
    if (i < NTOT) {
        int r = g_rowptr[i] + g_bsum[i >> 8];
        g_rowptr[i] = r;
        g_cursor[i] = r;
    }
    if (i == 0) g_rowptr[NTOT] = EDG;
}
__global__ void k_fill(const int* __restrict__ src, const int* __restrict__ dst) {
    int e = blockIdx.x*blockDim.x + threadIdx.x;
    if (e < EDG) {
        int d = dst[e];
        int s = src[e];
        int slot = atomicAdd(&g_cursor[d], 1);
        g_csr [slot] = s;
        g_coef[slot] = g_dinv[s]*g_dinv[d];
    }
}

// ---------------- GEMM: hW = X @ W ; bufA = bias + hW*dinv^2 (self-loop) ----------------
template<int F>
__device__ __forceinline__
void gemm_body(const float* __restrict__ X, const float* __restrict__ W,
               const float* __restrict__ bias) {
    __shared__ __align__(16) float4 ws[F*16];
    __shared__ __align__(16) float  bs[64];
    int tid = threadIdx.x;
    for (int i = tid; i < F*16; i += 256) ws[i] = ((const float4*)W)[i];
    if (tid < 64) bs[tid] = bias[tid];
    __syncthreads();

    int row = blockIdx.x*256 + tid;
    if (row >= NTOT) return;

    u64 acc[32];
    #pragma unroll
    for (int j = 0; j < 32; j++) acc[j] = 0ull;

    const float4* xp = (const float4*)(X + (size_t)row*F);
    #pragma unroll
    for (int c4 = 0; c4 < F/4; c4++) {
        float4 xv = xp[c4];
        int ci0 = c4*4;
        #pragma unroll
        for (int l = 0; l < 4; l++) {
            float xs = (l==0)?xv.x:(l==1)?xv.y:(l==2)?xv.z:xv.w;
            u64 xs2 = bcast2(xs);
            const u64* wrow = (const u64*)&ws[(ci0+l)*16];   // 32 packed pairs
            #pragma unroll
            for (int j = 0; j < 32; j++)
                acc[j] = ffma2(xs2, wrow[j], acc[j]);
        }
    }
    float dv = g_dinv[row];
    u64 d2_2 = bcast2(dv*dv);
    u64* hp = (u64*)(g_hW   + (size_t)row*64);
    u64* ap = (u64*)(g_bufA + (size_t)row*64);
    const u64* bs2 = (const u64*)bs;
    #pragma unroll
    for (int j = 0; j < 32; j++) {
        hp[j] = acc[j];
        ap[j] = ffma2(acc[j], d2_2, bs2[j]);   // acc*d2 + bias
    }
}

__global__ __launch_bounds__(256)
void k_gemm1(const float* __restrict__ X, const float* __restrict__ W,
             const float* __restrict__ bias) {
    gemm_body<F1>(X, W, bias);
}
// layer-2 GEMM: view rows of the flat [B,C,NN,T] tensor ARE contiguous 64-float
// chunks, so reading g_bufB at row*64 reproduces x.view(-1, 64) exactly.
__global__ __launch_bounds__(256)
void k_gemm2(const float* __restrict__ W, const float* __restrict__ bias) {
    gemm_body<CCH>(g_bufB, W, bias);
}

// ---------------- edge aggregation: warp per dst node, atomic-free --------------
// 4-wide unroll: 4 independent row loads in flight per iteration (avg degree 8
// -> ~2 iterations), halving exposed L2 latency vs the 2-wide loop.
__global__ __launch_bounds__(256)
void k_gather() {
    int g = blockIdx.x*blockDim.x + threadIdx.x;
    int node = g >> 5, lane = g & 31;
    if (node >= NTOT) return;
    int beg = g_rowptr[node], end = g_rowptr[node+1];
    float2* arow = (float2*)(g_bufA + (size_t)node*64);
    float2 acc = arow[lane];
    int j = beg;
    for (; j + 3 < end; j += 4) {
        int   s0 = g_csr [j],   s1 = g_csr [j+1],  s2 = g_csr [j+2],  s3 = g_csr [j+3];
        float c0 = g_coef[j],   c1 = g_coef[j+1];
        float c2 = g_coef[j+2], c3 = g_coef[j+3];
        float2 v0 = ((const float2*)(g_hW + (size_t)s0*64))[lane];
        float2 v1 = ((const float2*)(g_hW + (size_t)s1*64))[lane];
        float2 v2 = ((const float2*)(g_hW + (size_t)s2*64))[lane];
        float2 v3 = ((const float2*)(g_hW + (size_t)s3*64))[lane];
        acc.x += c0*v0.x + c1*v1.x + c2*v2.x + c3*v3.x;
        acc.y += c0*v0.y + c1*v1.y + c2*v2.y + c3*v3.y;
    }
    for (; j < end; j++) {
        int   s0 = g_csr [j];
        float c0 = g_coef[j];
        float2 v0 = ((const float2*)(g_hW + (size_t)s0*64))[lane];
        acc.x += c0*v0.x; acc.y += c0*v0.y;
    }
    arow[lane] = acc;
}

// ---------------- temporal conv (1x3 along T) + fused BN stats, bufA -> hW ----------
// Epilogue: each block reduces per-channel sum/sumsq of its 128x64 output tile into
// shared [128] then atomically accumulates into g_stats[0:128] (zeroed beforehand).
// This replaces the separate k_stats pass over 32MB.
#define IN_STRIDE 68
#define SMEM_CONV ((130*IN_STRIDE + 3*64*64 + 64 + 128) * 4)
__global__ __launch_bounds__(128)
void k_conv(const float* __restrict__ tw, const float* __restrict__ tb) {
    extern __shared__ float sm[];
    float* in_s = sm;                       // [130][68], row r = t+1
    float* w_s  = sm + 130*IN_STRIDE;       // [k][ci][co]  (offset 35360B, 16B-aligned)
    float* tb_s = w_s + 3*64*64;            // [64]
    float* s_sum = tb_s + 64;               // [64] per-block channel sums
    float* s_sq  = s_sum + 64;              // [64] per-block channel sumsq

    int bn = blockIdx.x;                    // 0..1023 = b*8+n
    int b = bn >> 3, n = bn & 7;
    int tid = threadIdx.x;

    for (int i = tid; i < 64*64*3; i += 128) {
        int co = i / 192, rem = i % 192, ci = rem / 3, k = rem % 3;
        w_s[(k*64 + ci)*64 + co] = tw[i];
    }
    if (tid < 64) tb_s[tid] = tb[tid];
    if (tid < 64) { s_sum[tid] = 0.f; s_sq[tid] = 0.f; }
    for (int i = tid; i < IN_STRIDE; i += 128) {
        in_s[i] = 0.f;
        in_s[129*IN_STRIDE + i] = 0.f;
    }
    const float* base = g_bufA + ((size_t)(b*TT_)*NN_ + n)*64;
    for (int i = tid; i < 128*16; i += 128) {
        int t = i >> 4, j = i & 15;
        float4 v = ((const float4*)(base + (size_t)t*NN_*64))[j];
        float* p = in_s + (t+1)*IN_STRIDE + j*4;
        p[0]=v.x; p[1]=v.y; p[2]=v.z; p[3]=v.w;
    }
    __syncthreads();

    int tg = tid >> 3, cg = tid & 7;
    int t0 = tg*8, co0 = cg*8;              // co0*4B = 32B -> 8B-aligned u64 loads ok
    u64 acc[8][4];
    {
        const u64* tb2 = (const u64*)(tb_s + co0);
        #pragma unroll
        for (int tt = 0; tt < 8; tt++)
            #pragma unroll
            for (int c2 = 0; c2 < 4; c2++) acc[tt][c2] = tb2[c2];
    }

    for (int ci = 0; ci < 64; ci++) {
        u64 xs2[10];
        #pragma unroll
        for (int i = 0; i < 10; i++) xs2[i] = bcast2(in_s[(t0+i)*IN_STRIDE + ci]);
        u64 wv2[12];
        #pragma unroll
        for (int k = 0; k < 3; k++) {
            const u64* wp = (const u64*)(w_s + ((k*64 + ci) << 6) + co0);
            wv2[k*4+0] = wp[0]; wv2[k*4+1] = wp[1];
            wv2[k*4+2] = wp[2]; wv2[k*4+3] = wp[3];
        }
        #pragma unroll
        for (int tt = 0; tt < 8; tt++)
            #pragma unroll
            for (int k = 0; k < 3; k++) {
                u64 x2 = xs2[tt+k];
                #pragma unroll
                for (int c2 = 0; c2 < 4; c2++)
                    acc[tt][c2] = ffma2(x2, wv2[k*4+c2], acc[tt][c2]);
            }
    }
    #pragma unroll
    for (int tt = 0; tt < 8; tt++) {
        u64* op = (u64*)(g_hW + (((size_t)((b*TT_ + t0+tt)*NN_ + n)) << 6) + co0);
        op[0] = acc[tt][0]; op[1] = acc[tt][1];
        op[2] = acc[tt][2]; op[3] = acc[tt][3];
    }

    // ---- fused BN partial stats (this thread owns cos co0..co0+7 over 8 t) ----
    #pragma unroll
    for (int c2 = 0; c2 < 4; c2++) {
        float slo = 0.f, qlo = 0.f, shi = 0.f, qhi = 0.f;
        #pragma unroll
        for (int tt = 0; tt < 8; tt++) {
            float lo = __uint_as_float((unsigned)acc[tt][c2]);
            float hi = __uint_as_float((unsigned)(acc[tt][c2] >> 32));
            slo += lo; qlo += lo*lo;
            shi += hi; qhi += hi*hi;
        }
        atomicAdd(&s_sum[co0 + 2*c2    ], slo);
        atomicAdd(&s_sq [co0 + 2*c2    ], qlo);
        atomicAdd(&s_sum[co0 + 2*c2 + 1], shi);
        atomicAdd(&s_sq [co0 + 2*c2 + 1], qhi);
    }
    __syncthreads();
    if (tid < 64) {
        atomicAdd(&g_stats[tid],      s_sum[tid]);
        atomicAdd(&g_stats[64 + tid], s_sq [tid]);
    }
}

// ---------------- BN stats zero / finalize ----------------
__global__ void k_zero_stats() {
    int t = threadIdx.x;
    if (t < 128) g_stats[t] = 0.f;
}
__global__ void k_stats_fin(const float* __restrict__ gam, const float* __restrict__ bet) {
    int c = threadIdx.x;
    if (c < 64) {
        float inv = 1.f/(float)NTOT;
        float mean = g_stats[c]*inv;
        float var  = g_stats[64+c]*inv - mean*mean;
        float a = gam[c]*rsqrtf(var + 1e-5f);
        g_stats[128+c] = a;
        g_stats[192+c] = bet[c] - mean*a;
    }
}

// ---------------- fused BN+ReLU+1x1conv+tanh : hW(rowmat) -> bufB(FLAT [B,C,NN,T]) ----
// Block = 256 consecutive rows r = (b, t in [t0,t0+32), n in [0,8)).
// Element (row=(b,t,n), co) -> flat offset ((b*64+co)*8+n)*128 + t.
#define RS 257
#define SMEM_FUSED (64*RS*4)
__global__ __launch_bounds__(256)
void k_fused(const float* __restrict__ ow, const float* __restrict__ ob) {
    __shared__ __align__(16) float wt[64*64];   // transposed [ci][co]
    __shared__ __align__(16) float sa[64];
    __shared__ __align__(16) float sb[64];
    __shared__ __align__(16) float sob[64];
    extern __shared__ float sm_t[];   // [64 co][RS rows]
    int tid = threadIdx.x;
    for (int i = tid; i < 4096; i += 256) {
        int co = i >> 6, ci = i & 63;
        wt[ci*64 + co] = ow[i];
    }
    if (tid < 64) {
        sa[tid] = g_stats[128+tid];
        sb[tid] = g_stats[192+tid];
        sob[tid] = ob[tid];
    }
    __syncthreads();

    int row = blockIdx.x*256 + tid;   // grid covers NTOT exactly
    const float4* yp = (const float4*)(g_hW + (size_t)row*64);
    u64 acc[32];
    {
        const u64* ob2 = (const u64*)sob;
        #pragma unroll
        for (int j = 0; j < 32; j++) acc[j] = ob2[j];
    }

    #pragma unroll
    for (int c4 = 0; c4 < 16; c4++) {
        float4 yv = yp[c4];
        int ci0 = c4*4;
        #pragma unroll
        for (int l = 0; l < 4; l++) {
            float y = (l==0)?yv.x:(l==1)?yv.y:(l==2)?yv.z:yv.w;
            int ci = ci0 + l;
            float u = fmaxf(sa[ci]*y + sb[ci], 0.f);
            u64 u2 = bcast2(u);
            const u64* wp = (const u64*)(wt + ci*64);
            #pragma unroll
            for (int j = 0; j < 32; j++)
                acc[j] = ffma2(u2, wp[j], acc[j]);
        }
    }
    // stage tanh output into smem tile: sm_t[co][tid], tid = tloc*8 + n
    #pragma unroll
    for (int j = 0; j < 32; j++) {
        float lo = __uint_as_float((unsigned)acc[j]);
        float hi = __uint_as_float((unsigned)(acc[j] >> 32));
        sm_t[(2*j  )*RS + tid] = tanhf(lo);
        sm_t[(2*j+1)*RS + tid] = tanhf(hi);
    }
    __syncthreads();

    // scatter to flat [B,C,NN,T]: each thread writes 2 runs of 32 contiguous t
    int b  = blockIdx.x >> 2;
    int t0 = (blockIdx.x & 3) * 32;
    #pragma unroll
    for (int k = 0; k < 2; k++) {
        int q  = k*256 + tid;           // run id: q = n*64 + co
        int n  = q >> 6, co = q & 63;
        float4* dp = (float4*)(g_bufB + (((size_t)(b*64 + co)*8 + n)*128 + t0));
        const float* sp = sm_t + co*RS + n;
        #pragma unroll
        for (int i = 0; i < 8; i++) {
            int tl = i*4;
            dp[i] = make_float4(sp[(tl+0)*8], sp[(tl+1)*8],
                                sp[(tl+2)*8], sp[(tl+3)*8]);
        }
    }
}

// ---------------- head: out[b,n] = (1/T) sum_t viewrow . wbar + bbar ----------------
__global__ void k_wbar(const float* __restrict__ rw, const float* __restrict__ rb) {
    int c = threadIdx.x;
    if (c < 64) {
        float s = 0.f;
        #pragma unroll
        for (int j = 0; j < 8; j++) s += rw[c*8 + j];
        g_wbar[c] = s*0.125f;
    }
    if (c == 64) {
        float s = 0.f;
        #pragma unroll
        for (int j = 0; j < 8; j++) s += rb[j];
        g_wbar[64] = s*0.125f;
    }
}
__global__ __launch_bounds__(128)
void k_head(float* __restrict__ out) {
    __shared__ float sw[64];
    __shared__ float red[128];
    int bn = blockIdx.x;                 // b*8+n
    int b = bn >> 3, n = bn & 7;
    int tid = threadIdx.x;               // = t
    if (tid < 64) sw[tid] = g_wbar[tid];
    __syncthreads();
    const float4* rp = (const float4*)(g_bufB + (((size_t)((b*TT_ + tid)*NN_ + n)) << 6));
    float s = 0.f;
    #pragma unroll
    for (int j = 0; j < 16; j++) {
        float4 v = rp[j];
        float4 w = ((const float4*)sw)[j];
        s += v.x*w.x + v.y*w.y + v.z*w.z + v.w*w.w;
    }
    red[tid] = s; __syncthreads();
    #pragma unroll
    for (int off = 64; off > 0; off >>= 1) {
        if (tid < off) red[tid] += red[tid+off];
        __syncthreads();
    }
    if (tid == 0) out[bn] = red[0]*(1.f/128.f) + g_wbar[64];
}

// ---------------- launch ----------------
extern "C" void kernel_launch(void* const* d_in, const int* in_sizes, int n_in,
                              void* d_out, int out_size) {
    const float* x      = (const float*)d_in[0];
    const int*   ei     = (const int*)d_in[1];
    const float* gcn1_w = (const float*)d_in[2];
    const float* gcn1_b = (const float*)d_in[3];
    const float* t1_w   = (const float*)d_in[4];
    const float* t1_b   = (const float*)d_in[5];
    const float* bn1_g  = (const float*)d_in[6];
    const float* bn1_b  = (const float*)d_in[7];
    const float* o1_w   = (const float*)d_in[8];
    const float* o1_b   = (const float*)d_in[9];
    const float* gcn2_w = (const float*)d_in[10];
    const float* gcn2_b = (const float*)d_in[11];
    const float* t2_w   = (const float*)d_in[12];
    const float* t2_b   = (const float*)d_in[13];
    const float* bn2_g  = (const float*)d_in[14];
    const float* bn2_b  = (const float*)d_in[15];
    const float* o2_w   = (const float*)d_in[16];
    const float* o2_b   = (const float*)d_in[17];
    const float* reg_w  = (const float*)d_in[18];
    const float* reg_b  = (const float*)d_in[19];
    const int* src = ei;
    const int* dst = ei + EDG;

    cudaFuncSetAttribute(k_conv,  cudaFuncAttributeMaxDynamicSharedMemorySize, SMEM_CONV);
    cudaFuncSetAttribute(k_fused, cudaFuncAttributeMaxDynamicSharedMemorySize, SMEM_FUSED);

    const int NBLK = NTOT/256;       // 512

    // graph normalization + CSR (shared by both layers)
    k_zero_deg<<<NBLK,256>>>();
    k_count<<<EDG/256,256>>>(dst);
    k_dinv<<<NBLK,256>>>();
    k_scan1<<<512,256>>>();
    k_scan2<<<1,512>>>();
    k_scan3<<<NBLK,256>>>();
    k_fill<<<EDG/256,256>>>(src, dst);

    // ---- layer 1 ----
    k_gemm1<<<NBLK,256>>>(x, gcn1_w, gcn1_b);
    k_gather<<<NTOT*32/256,256>>>();
    k_zero_stats<<<1,128>>>();
    k_conv<<<NB_*NN_,128,SMEM_CONV>>>(t1_w, t1_b);     // conv + fused BN stats
    k_stats_fin<<<1,64>>>(bn1_g, bn1_b);
    k_fused<<<NBLK,256,SMEM_FUSED>>>(o1_w, o1_b);

    // ---- layer 2 ----
    k_gemm2<<<NBLK,256>>>(gcn2_w, gcn2_b);
    k_gather<<<NTOT*32/256,256>>>();
    k_zero_stats<<<1,128>>>();
    k_conv<<<NB_*NN_,128,SMEM_CONV>>>(t2_w, t2_b);     // conv + fused BN stats
    k_stats_fin<<<1,64>>>(bn2_g, bn2_b);
    k_fused<<<NBLK,256,SMEM_FUSED>>>(o2_w, o2_b);

    // ---- head ----
    k_wbar<<<1,128>>>(reg_w, reg_b);
    k_head<<<NB_*NN_,128>>>((float*)d_out);
}